// round 14
// baseline (speedup 1.0000x reference)
#include <cuda_runtime.h>
#include <cuda_fp16.h>
#include <cstdint>

// ============================================================================
// y[t, :] = weight[x[t], :] + A[x[t], :] @ B
//   tokens M = 16384, DIM N = 1024, RANK K = 256
// Fragment-direct mainloop (no smem operands, no barriers), now at 3 CTAs/SM:
//   TILE 128x64, 8 warps, warp tile 32x32 -> acc 32 regs, ~84 regs total.
//   g_Af[mb][ks][lane] / g_Bf[nb][ks][lane] = uint4 MMA fragments.
// Weight tile cp.async-staged at tile start, covered by the whole mainloop.
// ============================================================================
static constexpr int M_TOTAL = 16384;
static constexpr int DIM     = 1024;
static constexpr int RANK    = 256;

static constexpr int TILE_M  = 128;
static constexpr int TILE_N  = 64;

// Smem: weight tile only. 128 rows x 272 B (68 floats).
static constexpr int W_PITCH_F  = 68;
static constexpr int W_PITCH_BY = 272;
static constexpr int SMEM_BYTES = TILE_M * W_PITCH_BY + 64;   // 34880 B

// Fragment scratch
__device__ uint4 g_Af[(M_TOTAL / 16) * 16 * 32];   // [mb][ks][lane], 8 MB
__device__ uint4 g_Bf[(DIM / 16) * 16 * 32];       // [nb][ks][lane], 0.5 MB

// ---------------------------------------------------------------------------
__device__ __forceinline__ uint32_t smem_to_u32(const void* p) {
    uint32_t a;
    asm("{ .reg .u64 t; cvta.to.shared.u64 t, %1; cvt.u32.u64 %0, t; }" : "=r"(a) : "l"(p));
    return a;
}
__device__ __forceinline__ void cp_async16(uint32_t dst, const void* src) {
    asm volatile("cp.async.cg.shared.global [%0], [%1], 16;" :: "r"(dst), "l"(src));
}
__device__ __forceinline__ void cp_commit() {
    asm volatile("cp.async.commit_group;" ::: "memory");
}
template <int N>
__device__ __forceinline__ void cp_wait() {
    asm volatile("cp.async.wait_group %0;" :: "n"(N) : "memory");
}
__device__ __forceinline__ void mma_f16(float* c, const uint32_t* a, const uint32_t* b) {
    asm volatile(
        "mma.sync.aligned.m16n8k16.row.col.f32.f16.f16.f32 "
        "{%0,%1,%2,%3}, {%4,%5,%6,%7}, {%8,%9}, {%0,%1,%2,%3};\n"
        : "+f"(c[0]), "+f"(c[1]), "+f"(c[2]), "+f"(c[3])
        : "r"(a[0]), "r"(a[1]), "r"(a[2]), "r"(a[3]), "r"(b[0]), "r"(b[1]));
}
__device__ __forceinline__ void stg_cs_v2(float* p, float x, float y) {
    asm volatile("st.global.cs.v2.f32 [%0], {%1,%2};" :: "l"(p), "f"(x), "f"(y) : "memory");
}
__device__ __forceinline__ uint32_t h2u(float a, float b) {
    __half2 h = __floats2half2_rn(a, b);
    return *(uint32_t*)&h;
}

// ============================================================================
// Kernel 1 (fused prep):
//   blocks [0,64):       B fragmentizer (as R13).
//   blocks [64,64+2048): A fragment gather (as R12/R13).
// ============================================================================
__global__ __launch_bounds__(256)
void prep_kernel(const int* __restrict__ x, const float* __restrict__ A,
                 const float* __restrict__ B) {
    if (blockIdx.x < 64) {
        __shared__ float sB[256 * 20];             // [k][n], pitch 20 floats
        const int nb  = blockIdx.x;
        const int tid = threadIdx.x;
        {
            const float4* src = (const float4*)(B + (size_t)tid * DIM + nb * 16);
            float4* dst = (float4*)(sB + tid * 20);
            #pragma unroll
            for (int i = 0; i < 4; i++) dst[i] = src[i];
        }
        __syncthreads();
        const int wid  = tid >> 5;
        const int lane = tid & 31;
        const int g    = lane >> 2;
        const int t    = lane & 3;
        #pragma unroll
        for (int h = 0; h < 2; h++) {
            const int ks = wid + h * 8;            // 0..15
            const int k0 = ks * 16 + 2 * t;
            uint4 v;
            v.x = h2u(sB[(k0 + 0) * 20 + g],     sB[(k0 + 1) * 20 + g]);
            v.y = h2u(sB[(k0 + 8) * 20 + g],     sB[(k0 + 9) * 20 + g]);
            v.z = h2u(sB[(k0 + 0) * 20 + g + 8], sB[(k0 + 1) * 20 + g + 8]);
            v.w = h2u(sB[(k0 + 8) * 20 + g + 8], sB[(k0 + 9) * 20 + g + 8]);
            g_Bf[(nb * 16 + ks) * 32 + lane] = v;
        }
    } else {
        const int blk  = blockIdx.x - 64;                  // 0..2047
        const int mb   = blk >> 1;                         // 0..1023
        const int ks   = ((blk & 1) << 3) + (threadIdx.x >> 5);  // 0..15
        const int lane = threadIdx.x & 31;
        const int r    = lane >> 2;
        const int c    = ks * 16 + (lane & 3) * 2;
        const int tok_lo = x[mb * 16 + r];
        const int tok_hi = x[mb * 16 + 8 + r];
        const float* alo = A + (size_t)tok_lo * RANK;
        const float* ahi = A + (size_t)tok_hi * RANK;
        const float2 f0 = *(const float2*)(alo + c);
        const float2 f1 = *(const float2*)(ahi + c);
        const float2 f2 = *(const float2*)(alo + c + 8);
        const float2 f3 = *(const float2*)(ahi + c + 8);
        uint4 v;
        v.x = h2u(f0.x, f0.y);
        v.y = h2u(f1.x, f1.y);
        v.z = h2u(f2.x, f2.y);
        v.w = h2u(f3.x, f3.y);
        g_Af[(mb * 16 + ks) * 32 + lane] = v;
    }
#if __CUDA_ARCH__ >= 900
    cudaTriggerProgrammaticLaunchCompletion();
#endif
}

// ============================================================================
// Kernel 2: fused GEMM + weight epilogue
//   grid: (16, 128) N fastest; block 256 = 8 warps; warp grid 4(M) x 2(N),
//   warp tile 32x32; 3 CTAs/SM. Mainloop: LDG fragments + MMA, no barriers.
// ============================================================================
__global__ __launch_bounds__(256, 3)
void lora_embed_kernel(const int* __restrict__ x,
                       const float* __restrict__ weight,
                       float* __restrict__ out) {
    extern __shared__ __align__(16) char smem[];

    const int tid    = threadIdx.x;
    const int wid    = tid >> 5;
    const int lane   = tid & 31;
    const int group  = lane >> 2;   // 0..7
    const int tig    = lane & 3;    // 0..3
    const int warp_m = wid >> 1;    // 0..3
    const int warp_n = wid & 1;     // 0..1

    const int n0 = blockIdx.x * TILE_N;
    const int m0 = blockIdx.y * TILE_M;

    const uint32_t sb = smem_to_u32(smem);

    // Weight stager: 128 rows x 16 x 16B chunks = 2048 units, 8 per thread.
    auto stage_weight = [&]() {
        #pragma unroll
        for (int i = 0; i < 8; i++) {
            const int idx = tid + 256 * i;       // 0..2047
            const int row = idx >> 4;            // 0..127
            const int c16 = idx & 15;            // 16B chunk in 256B row
            const int tok = x[m0 + row];         // 16 threads/row -> broadcast
            cp_async16(sb + (uint32_t)(row * W_PITCH_BY + c16 * 16),
                       weight + (size_t)tok * DIM + n0 + c16 * 4);
        }
        cp_commit();
    };

    // Fragment pointers. ks stride 512 B; block(16-row/col) stride 8192 B.
    const char* aptr = (const char*)g_Af
        + ((size_t)(blockIdx.y * 8 + warp_m * 2) * 16 * 32 + lane) * 16;
    const char* bptr = (const char*)g_Bf
        + ((size_t)(blockIdx.x * 4 + warp_n * 2) * 16 * 32 + lane) * 16;

    float acc[2][4][4];
    #pragma unroll
    for (int mt = 0; mt < 2; mt++)
        #pragma unroll
        for (int nt = 0; nt < 4; nt++)
            #pragma unroll
            for (int r = 0; r < 4; r++) acc[mt][nt][r] = 0.f;

    uint4 af[2][2];
    uint4 bv[2][2];

    auto load_frags = [&](int buf, int ks) {
        #pragma unroll
        for (int mt = 0; mt < 2; mt++)
            af[buf][mt] = *(const uint4*)(aptr + mt * 8192 + ks * 512);
        #pragma unroll
        for (int q = 0; q < 2; q++)
            bv[buf][q] = *(const uint4*)(bptr + q * 8192 + ks * 512);
    };

    // Start weight staging (covered by the whole mainloop).
    stage_weight();

    // PDL: block before first read of g_Af/g_Bf.
#if __CUDA_ARCH__ >= 900
    cudaGridDependencySynchronize();
#endif

    load_frags(0, 0);

    // Mainloop: 16 k-steps, 1-step lookahead, zero barriers.
    #pragma unroll
    for (int ks = 0; ks < 16; ks++) {
        if (ks + 1 < 16) load_frags((ks + 1) & 1, ks + 1);
        const uint32_t* a0 = (const uint32_t*)&af[ks & 1][0];
        const uint32_t* a1 = (const uint32_t*)&af[ks & 1][1];
        #pragma unroll
        for (int q = 0; q < 2; q++) {
            const uint32_t* bp = (const uint32_t*)&bv[ks & 1][q];
            mma_f16(acc[0][2 * q + 0], a0, bp + 0);
            mma_f16(acc[0][2 * q + 1], a0, bp + 2);
            mma_f16(acc[1][2 * q + 0], a1, bp + 0);
            mma_f16(acc[1][2 * q + 1], a1, bp + 2);
        }
    }

    // Weight must be resident now (staged a whole mainloop ago).
    cp_wait<0>();
    __syncthreads();

    // Epilogue: out = weight_smem + acc.
    const float* wsm = (const float*)smem;
    #pragma unroll
    for (int mt = 0; mt < 2; mt++) {
        #pragma unroll
        for (int mo = 0; mo < 2; mo++) {
            const int r = warp_m * 32 + mt * 16 + mo * 8 + group;   // 0..127
            const float* wrow = wsm + r * W_PITCH_F;
            float* orow = out + (size_t)(m0 + r) * DIM + n0;
            #pragma unroll
            for (int nt = 0; nt < 4; nt++) {
                const int col = warp_n * 32 + nt * 8 + tig * 2;     // 0..63
                float2 w = *(const float2*)(wrow + col);
                stg_cs_v2(orow + col,
                          w.x + acc[mt][nt][mo * 2 + 0],
                          w.y + acc[mt][nt][mo * 2 + 1]);
            }
        }
    }
}

// ============================================================================
// Launch
// ============================================================================
extern "C" void kernel_launch(void* const* d_in, const int* in_sizes, int n_in,
                              void* d_out, int out_size) {
    const int*   x      = (const int*)d_in[0];       // [16384] int32
    const float* weight = (const float*)d_in[1];     // [128000, 1024]
    const float* A      = (const float*)d_in[2];     // [128000, 256]
    const float* B      = (const float*)d_in[3];     // [256, 1024]
    float* out          = (float*)d_out;             // [16384, 1024]

    (void)in_sizes; (void)n_in; (void)out_size;

    // Fused prep: 64 B-fragment blocks + 2048 A-fragment blocks
    prep_kernel<<<64 + 2048, 256>>>(x, A, B);

    {
        static bool attr_set = false;
        if (!attr_set) {
            cudaFuncSetAttribute(lora_embed_kernel,
                                 cudaFuncAttributeMaxDynamicSharedMemorySize, SMEM_BYTES);
            attr_set = true;
        }
        cudaLaunchConfig_t cfg = {};
        cfg.gridDim  = dim3(DIM / TILE_N, M_TOTAL / TILE_M);   // (16, 128)
        cfg.blockDim = dim3(256, 1, 1);
        cfg.dynamicSmemBytes = SMEM_BYTES;
        cfg.stream = 0;
        cudaLaunchAttribute attrs[1];
        attrs[0].id = cudaLaunchAttributeProgrammaticStreamSerialization;
        attrs[0].val.programmaticStreamSerializationAllowed = 1;
        cfg.attrs = attrs;
        cfg.numAttrs = 1;
        cudaError_t err = cudaLaunchKernelEx(&cfg, lora_embed_kernel, x, weight, out);
        if (err != cudaSuccess) {
            cudaGetLastError();
            dim3 grid(DIM / TILE_N, M_TOTAL / TILE_M);
            lora_embed_kernel<<<grid, 256, SMEM_BYTES>>>(x, weight, out);
        }
    }
}

// round 15
// speedup vs baseline: 1.0050x; 1.0050x over previous
#include <cuda_runtime.h>
#include <cuda_fp16.h>
#include <cstdint>

// ============================================================================
// y[t, :] = weight[x[t], :] + A[x[t], :] @ B
//   tokens M = 16384, DIM N = 1024, RANK K = 256
// Fragment-direct mainloop (no smem operands, no barriers), 3 CTAs/SM:
//   TILE 128x64, 8 warps, warp tile 32x32, ~76 regs.
//   g_Af[mb][ks][lane] / g_Bf[nb][ks][lane] = uint4 MMA fragments.
// Weight staging moved INTO the mainloop (ks==4) so its 33KB cp.async burst
// no longer queues ahead of the first fragment loads (R5 lesson).
// Prep: A rows gathered COALESCED through smem (1KB runs), then fragmentized.
// ============================================================================
static constexpr int M_TOTAL = 16384;
static constexpr int DIM     = 1024;
static constexpr int RANK    = 256;

static constexpr int TILE_M  = 128;
static constexpr int TILE_N  = 64;

// Smem (main): weight tile only. 128 rows x 272 B (68 floats).
static constexpr int W_PITCH_F  = 68;
static constexpr int W_PITCH_BY = 272;
static constexpr int SMEM_BYTES = TILE_M * W_PITCH_BY + 64;   // 34880 B

// Fragment scratch
__device__ uint4 g_Af[(M_TOTAL / 16) * 16 * 32];   // [mb][ks][lane], 8 MB
__device__ uint4 g_Bf[(DIM / 16) * 16 * 32];       // [nb][ks][lane], 0.5 MB

// ---------------------------------------------------------------------------
__device__ __forceinline__ uint32_t smem_to_u32(const void* p) {
    uint32_t a;
    asm("{ .reg .u64 t; cvta.to.shared.u64 t, %1; cvt.u32.u64 %0, t; }" : "=r"(a) : "l"(p));
    return a;
}
__device__ __forceinline__ void cp_async16(uint32_t dst, const void* src) {
    asm volatile("cp.async.cg.shared.global [%0], [%1], 16;" :: "r"(dst), "l"(src));
}
__device__ __forceinline__ void cp_commit() {
    asm volatile("cp.async.commit_group;" ::: "memory");
}
template <int N>
__device__ __forceinline__ void cp_wait() {
    asm volatile("cp.async.wait_group %0;" :: "n"(N) : "memory");
}
__device__ __forceinline__ void mma_f16(float* c, const uint32_t* a, const uint32_t* b) {
    asm volatile(
        "mma.sync.aligned.m16n8k16.row.col.f32.f16.f16.f32 "
        "{%0,%1,%2,%3}, {%4,%5,%6,%7}, {%8,%9}, {%0,%1,%2,%3};\n"
        : "+f"(c[0]), "+f"(c[1]), "+f"(c[2]), "+f"(c[3])
        : "r"(a[0]), "r"(a[1]), "r"(a[2]), "r"(a[3]), "r"(b[0]), "r"(b[1]));
}
__device__ __forceinline__ void stg_cs_v2(float* p, float x, float y) {
    asm volatile("st.global.cs.v2.f32 [%0], {%1,%2};" :: "l"(p), "f"(x), "f"(y) : "memory");
}
__device__ __forceinline__ uint32_t h2u(float a, float b) {
    __half2 h = __floats2half2_rn(a, b);
    return *(uint32_t*)&h;
}

// ============================================================================
// Kernel 1 (fused prep):
//   blocks [0,64):     B fragmentizer (as R13/R14).
//   blocks [64,64+512): A fragment gather, COALESCED:
//     block handles 2 mb (32 token rows). Phase 1: gather 32 rows x 1KB into
//     smem via fully-coalesced LDG.128 (threads sweep each row contiguously).
//     Phase 2: each warp emits fragments for 4 (mb,ks) pairs from smem.
// Fragment uint4 (lane l, g=l>>2, t=l&3):
//   v = (row g k0k1, row g+8 k0k1, row g k8k9, row g+8 k8k9), k0 = ks*16+2t.
// ============================================================================
__global__ __launch_bounds__(256)
void prep_kernel(const int* __restrict__ x, const float* __restrict__ A,
                 const float* __restrict__ B) {
    if (blockIdx.x < 64) {
        // ---- B fragmentizer ----
        __shared__ float sB[256 * 20];             // [k][n], pitch 20 floats
        const int nb  = blockIdx.x;
        const int tid = threadIdx.x;
        {
            const float4* src = (const float4*)(B + (size_t)tid * DIM + nb * 16);
            float4* dst = (float4*)(sB + tid * 20);
            #pragma unroll
            for (int i = 0; i < 4; i++) dst[i] = src[i];
        }
        __syncthreads();
        const int wid  = tid >> 5;
        const int lane = tid & 31;
        const int g    = lane >> 2;
        const int t    = lane & 3;
        #pragma unroll
        for (int h = 0; h < 2; h++) {
            const int ks = wid + h * 8;            // 0..15
            const int k0 = ks * 16 + 2 * t;
            uint4 v;
            v.x = h2u(sB[(k0 + 0) * 20 + g],     sB[(k0 + 1) * 20 + g]);
            v.y = h2u(sB[(k0 + 8) * 20 + g],     sB[(k0 + 9) * 20 + g]);
            v.z = h2u(sB[(k0 + 0) * 20 + g + 8], sB[(k0 + 1) * 20 + g + 8]);
            v.w = h2u(sB[(k0 + 8) * 20 + g + 8], sB[(k0 + 9) * 20 + g + 8]);
            g_Bf[(nb * 16 + ks) * 32 + lane] = v;
        }
    } else {
        // ---- A coalesced gather + fragmentize ----
        __shared__ float sA[32 * 260];             // 32 rows, pitch 260 floats
        const int blk  = blockIdx.x - 64;          // 0..511
        const int mb0  = blk * 2;                  // first of 2 mb handled
        const int tid  = threadIdx.x;

        // Phase 1: 32 rows x 64 float4 = 2048 float4; 8 per thread.
        // Row r is read by 64 consecutive threads -> 1KB coalesced runs.
        #pragma unroll
        for (int i = 0; i < 8; i++) {
            const int idx  = tid + 256 * i;        // 0..2047
            const int row  = idx >> 6;             // 0..31
            const int col4 = idx & 63;             // float4 index in row
            const int tok  = x[mb0 * 16 + row];
            *(float4*)(sA + row * 260 + col4 * 4) =
                *(const float4*)(A + (size_t)tok * RANK + col4 * 4);
        }
        __syncthreads();

        // Phase 2: 32 (mb_local, ks) pairs; warp w emits pairs w*4..w*4+3.
        const int wid  = tid >> 5;
        const int lane = tid & 31;
        const int g    = lane >> 2;
        const int t    = lane & 3;
        #pragma unroll
        for (int p = 0; p < 4; p++) {
            const int pair = wid * 4 + p;          // 0..31
            const int ml   = pair >> 4;            // mb_local 0..1
            const int ks   = pair & 15;
            const int c    = ks * 16 + 2 * t;
            const float* rlo = sA + (ml * 16 + g) * 260;
            const float* rhi = sA + (ml * 16 + 8 + g) * 260;
            uint4 v;
            v.x = h2u(rlo[c],     rlo[c + 1]);
            v.y = h2u(rhi[c],     rhi[c + 1]);
            v.z = h2u(rlo[c + 8], rlo[c + 9]);
            v.w = h2u(rhi[c + 8], rhi[c + 9]);
            g_Af[((mb0 + ml) * 16 + ks) * 32 + lane] = v;
        }
    }
#if __CUDA_ARCH__ >= 900
    cudaTriggerProgrammaticLaunchCompletion();
#endif
}

// ============================================================================
// Kernel 2: fused GEMM + weight epilogue
//   grid: (16, 128) N fastest; block 256 = 8 warps; warp grid 4(M) x 2(N),
//   warp tile 32x32; 3 CTAs/SM. Mainloop: LDG fragments + MMA, no barriers.
//   Weight staged mid-loop (ks==4) to keep the LSU clear at loop entry.
// ============================================================================
__global__ __launch_bounds__(256, 3)
void lora_embed_kernel(const int* __restrict__ x,
                       const float* __restrict__ weight,
                       float* __restrict__ out) {
    extern __shared__ __align__(16) char smem[];

    const int tid    = threadIdx.x;
    const int wid    = tid >> 5;
    const int lane   = tid & 31;
    const int group  = lane >> 2;   // 0..7
    const int tig    = lane & 3;    // 0..3
    const int warp_m = wid >> 1;    // 0..3
    const int warp_n = wid & 1;     // 0..1

    const int n0 = blockIdx.x * TILE_N;
    const int m0 = blockIdx.y * TILE_M;

    const uint32_t sb = smem_to_u32(smem);

    // Weight stager: 128 rows x 16 x 16B chunks = 2048 units, 8 per thread.
    auto stage_weight = [&]() {
        #pragma unroll
        for (int i = 0; i < 8; i++) {
            const int idx = tid + 256 * i;       // 0..2047
            const int row = idx >> 4;            // 0..127
            const int c16 = idx & 15;            // 16B chunk in 256B row
            const int tok = x[m0 + row];         // 16 threads/row -> broadcast
            cp_async16(sb + (uint32_t)(row * W_PITCH_BY + c16 * 16),
                       weight + (size_t)tok * DIM + n0 + c16 * 4);
        }
        cp_commit();
    };

    // Fragment pointers. ks stride 512 B; 16-row/col block stride 8192 B.
    const char* aptr = (const char*)g_Af
        + ((size_t)(blockIdx.y * 8 + warp_m * 2) * 16 * 32 + lane) * 16;
    const char* bptr = (const char*)g_Bf
        + ((size_t)(blockIdx.x * 4 + warp_n * 2) * 16 * 32 + lane) * 16;

    float acc[2][4][4];
    #pragma unroll
    for (int mt = 0; mt < 2; mt++)
        #pragma unroll
        for (int nt = 0; nt < 4; nt++)
            #pragma unroll
            for (int r = 0; r < 4; r++) acc[mt][nt][r] = 0.f;

    uint4 af[2][2];
    uint4 bv[2][2];

    auto load_frags = [&](int buf, int ks) {
        #pragma unroll
        for (int mt = 0; mt < 2; mt++)
            af[buf][mt] = *(const uint4*)(aptr + mt * 8192 + ks * 512);
        #pragma unroll
        for (int q = 0; q < 2; q++)
            bv[buf][q] = *(const uint4*)(bptr + q * 8192 + ks * 512);
    };

    // PDL: block before first read of g_Af/g_Bf.
#if __CUDA_ARCH__ >= 900
    cudaGridDependencySynchronize();
#endif

    load_frags(0, 0);

    // Mainloop: 16 k-steps, 1-step lookahead, zero barriers.
    // Weight staging issued at ks==4: the pipeline is warm, and its 33KB
    // cp.async burst no longer delays the first fragment loads; it is still
    // covered by 12 k-steps before the epilogue's wait.
    #pragma unroll
    for (int ks = 0; ks < 16; ks++) {
        if (ks + 1 < 16) load_frags((ks + 1) & 1, ks + 1);
        if (ks == 4) stage_weight();
        const uint32_t* a0 = (const uint32_t*)&af[ks & 1][0];
        const uint32_t* a1 = (const uint32_t*)&af[ks & 1][1];
        #pragma unroll
        for (int q = 0; q < 2; q++) {
            const uint32_t* bp = (const uint32_t*)&bv[ks & 1][q];
            mma_f16(acc[0][2 * q + 0], a0, bp + 0);
            mma_f16(acc[0][2 * q + 1], a0, bp + 2);
            mma_f16(acc[1][2 * q + 0], a1, bp + 0);
            mma_f16(acc[1][2 * q + 1], a1, bp + 2);
        }
    }

    // Weight resident (staged 12 k-steps ago).
    cp_wait<0>();
    __syncthreads();

    // Epilogue: out = weight_smem + acc.
    const float* wsm = (const float*)smem;
    #pragma unroll
    for (int mt = 0; mt < 2; mt++) {
        #pragma unroll
        for (int mo = 0; mo < 2; mo++) {
            const int r = warp_m * 32 + mt * 16 + mo * 8 + group;   // 0..127
            const float* wrow = wsm + r * W_PITCH_F;
            float* orow = out + (size_t)(m0 + r) * DIM + n0;
            #pragma unroll
            for (int nt = 0; nt < 4; nt++) {
                const int col = warp_n * 32 + nt * 8 + tig * 2;     // 0..63
                float2 w = *(const float2*)(wrow + col);
                stg_cs_v2(orow + col,
                          w.x + acc[mt][nt][mo * 2 + 0],
                          w.y + acc[mt][nt][mo * 2 + 1]);
            }
        }
    }
}

// ============================================================================
// Launch
// ============================================================================
extern "C" void kernel_launch(void* const* d_in, const int* in_sizes, int n_in,
                              void* d_out, int out_size) {
    const int*   x      = (const int*)d_in[0];       // [16384] int32
    const float* weight = (const float*)d_in[1];     // [128000, 1024]
    const float* A      = (const float*)d_in[2];     // [128000, 256]
    const float* B      = (const float*)d_in[3];     // [256, 1024]
    float* out          = (float*)d_out;             // [16384, 1024]

    (void)in_sizes; (void)n_in; (void)out_size;

    // Fused prep: 64 B-fragment blocks + 512 coalesced A-fragment blocks
    prep_kernel<<<64 + 512, 256>>>(x, A, B);

    {
        static bool attr_set = false;
        if (!attr_set) {
            cudaFuncSetAttribute(lora_embed_kernel,
                                 cudaFuncAttributeMaxDynamicSharedMemorySize, SMEM_BYTES);
            attr_set = true;
        }
        cudaLaunchConfig_t cfg = {};
        cfg.gridDim  = dim3(DIM / TILE_N, M_TOTAL / TILE_M);   // (16, 128)
        cfg.blockDim = dim3(256, 1, 1);
        cfg.dynamicSmemBytes = SMEM_BYTES;
        cfg.stream = 0;
        cudaLaunchAttribute attrs[1];
        attrs[0].id = cudaLaunchAttributeProgrammaticStreamSerialization;
        attrs[0].val.programmaticStreamSerializationAllowed = 1;
        cfg.attrs = attrs;
        cfg.numAttrs = 1;
        cudaError_t err = cudaLaunchKernelEx(&cfg, lora_embed_kernel, x, weight, out);
        if (err != cudaSuccess) {
            cudaGetLastError();
            dim3 grid(DIM / TILE_N, M_TOTAL / TILE_M);
            lora_embed_kernel<<<grid, 256, SMEM_BYTES>>>(x, weight, out);
        }
    }
}

// round 16
// speedup vs baseline: 1.0464x; 1.0413x over previous
#include <cuda_runtime.h>
#include <cuda_fp16.h>
#include <cstdint>

// ============================================================================
// y[t, :] = weight[x[t], :] + A[x[t], :] @ B
//   tokens M = 16384, DIM N = 1024, RANK K = 256
// Fragment-direct mainloop (no smem operands, no barriers), 3 CTAs/SM:
//   TILE 128x64, 8 warps, warp tile 32x32, ~80 regs.
//   g_Af[mb][ks][lane] / g_Bf[nb][ks][lane] = uint4 MMA fragments.
// Weight staged mid-loop (ks==4). Prep: direct scattered A-fragment gather
// (R13 form — measured faster than the smem-coalesced variant).
// ============================================================================
static constexpr int M_TOTAL = 16384;
static constexpr int DIM     = 1024;
static constexpr int RANK    = 256;

static constexpr int TILE_M  = 128;
static constexpr int TILE_N  = 64;

// Smem (main): weight tile only. 128 rows x 272 B (68 floats).
static constexpr int W_PITCH_F  = 68;
static constexpr int W_PITCH_BY = 272;
static constexpr int SMEM_BYTES = TILE_M * W_PITCH_BY + 64;   // 34880 B

// Fragment scratch
__device__ uint4 g_Af[(M_TOTAL / 16) * 16 * 32];   // [mb][ks][lane], 8 MB
__device__ uint4 g_Bf[(DIM / 16) * 16 * 32];       // [nb][ks][lane], 0.5 MB

// ---------------------------------------------------------------------------
__device__ __forceinline__ uint32_t smem_to_u32(const void* p) {
    uint32_t a;
    asm("{ .reg .u64 t; cvta.to.shared.u64 t, %1; cvt.u32.u64 %0, t; }" : "=r"(a) : "l"(p));
    return a;
}
__device__ __forceinline__ void cp_async16(uint32_t dst, const void* src) {
    asm volatile("cp.async.cg.shared.global [%0], [%1], 16;" :: "r"(dst), "l"(src));
}
__device__ __forceinline__ void cp_commit() {
    asm volatile("cp.async.commit_group;" ::: "memory");
}
template <int N>
__device__ __forceinline__ void cp_wait() {
    asm volatile("cp.async.wait_group %0;" :: "n"(N) : "memory");
}
__device__ __forceinline__ void mma_f16(float* c, const uint32_t* a, const uint32_t* b) {
    asm volatile(
        "mma.sync.aligned.m16n8k16.row.col.f32.f16.f16.f32 "
        "{%0,%1,%2,%3}, {%4,%5,%6,%7}, {%8,%9}, {%0,%1,%2,%3};\n"
        : "+f"(c[0]), "+f"(c[1]), "+f"(c[2]), "+f"(c[3])
        : "r"(a[0]), "r"(a[1]), "r"(a[2]), "r"(a[3]), "r"(b[0]), "r"(b[1]));
}
__device__ __forceinline__ void stg_cs_v2(float* p, float x, float y) {
    asm volatile("st.global.cs.v2.f32 [%0], {%1,%2};" :: "l"(p), "f"(x), "f"(y) : "memory");
}
__device__ __forceinline__ uint32_t h2u(float a, float b) {
    __half2 h = __floats2half2_rn(a, b);
    return *(uint32_t*)&h;
}

// ============================================================================
// Kernel 1 (fused prep):
//   blocks [0,64):       B fragmentizer (padded-smem transpose form).
//   blocks [64,64+2048): A fragment gather, DIRECT scattered (R13 form):
//     block b: mb = b>>1; warp w handles ks = (b&1)*8 + w; lane l emits the
//     uint4 that mma.m16n8k16 expects: rows (l>>2, l>>2+8) x k (2(l&3), +8).
// ============================================================================
__global__ __launch_bounds__(256)
void prep_kernel(const int* __restrict__ x, const float* __restrict__ A,
                 const float* __restrict__ B) {
    if (blockIdx.x < 64) {
        // ---- B fragmentizer ----
        __shared__ float sB[256 * 20];             // [k][n], pitch 20 floats
        const int nb  = blockIdx.x;
        const int tid = threadIdx.x;
        {
            const float4* src = (const float4*)(B + (size_t)tid * DIM + nb * 16);
            float4* dst = (float4*)(sB + tid * 20);
            #pragma unroll
            for (int i = 0; i < 4; i++) dst[i] = src[i];
        }
        __syncthreads();
        const int wid  = tid >> 5;
        const int lane = tid & 31;
        const int g    = lane >> 2;
        const int t    = lane & 3;
        #pragma unroll
        for (int h = 0; h < 2; h++) {
            const int ks = wid + h * 8;            // 0..15
            const int k0 = ks * 16 + 2 * t;
            uint4 v;
            v.x = h2u(sB[(k0 + 0) * 20 + g],     sB[(k0 + 1) * 20 + g]);
            v.y = h2u(sB[(k0 + 8) * 20 + g],     sB[(k0 + 9) * 20 + g]);
            v.z = h2u(sB[(k0 + 0) * 20 + g + 8], sB[(k0 + 1) * 20 + g + 8]);
            v.w = h2u(sB[(k0 + 8) * 20 + g + 8], sB[(k0 + 9) * 20 + g + 8]);
            g_Bf[(nb * 16 + ks) * 32 + lane] = v;
        }
    } else {
        // ---- A fragment gather (direct scattered) ----
        const int blk  = blockIdx.x - 64;                  // 0..2047
        const int mb   = blk >> 1;                         // 0..1023
        const int ks   = ((blk & 1) << 3) + (threadIdx.x >> 5);  // 0..15
        const int lane = threadIdx.x & 31;
        const int r    = lane >> 2;
        const int c    = ks * 16 + (lane & 3) * 2;
        const int tok_lo = x[mb * 16 + r];
        const int tok_hi = x[mb * 16 + 8 + r];
        const float* alo = A + (size_t)tok_lo * RANK;
        const float* ahi = A + (size_t)tok_hi * RANK;
        const float2 f0 = *(const float2*)(alo + c);
        const float2 f1 = *(const float2*)(ahi + c);
        const float2 f2 = *(const float2*)(alo + c + 8);
        const float2 f3 = *(const float2*)(ahi + c + 8);
        uint4 v;
        v.x = h2u(f0.x, f0.y);
        v.y = h2u(f1.x, f1.y);
        v.z = h2u(f2.x, f2.y);
        v.w = h2u(f3.x, f3.y);
        g_Af[(mb * 16 + ks) * 32 + lane] = v;
    }
#if __CUDA_ARCH__ >= 900
    cudaTriggerProgrammaticLaunchCompletion();
#endif
}

// ============================================================================
// Kernel 2: fused GEMM + weight epilogue  (R15 main, unchanged)
//   grid: (16, 128) N fastest; block 256 = 8 warps; warp grid 4(M) x 2(N),
//   warp tile 32x32; 3 CTAs/SM. Mainloop: LDG fragments + MMA, no barriers.
//   Weight staged mid-loop (ks==4) to keep the LSU clear at loop entry.
// ============================================================================
__global__ __launch_bounds__(256, 3)
void lora_embed_kernel(const int* __restrict__ x,
                       const float* __restrict__ weight,
                       float* __restrict__ out) {
    extern __shared__ __align__(16) char smem[];

    const int tid    = threadIdx.x;
    const int wid    = tid >> 5;
    const int lane   = tid & 31;
    const int group  = lane >> 2;   // 0..7
    const int tig    = lane & 3;    // 0..3
    const int warp_m = wid >> 1;    // 0..3
    const int warp_n = wid & 1;     // 0..1

    const int n0 = blockIdx.x * TILE_N;
    const int m0 = blockIdx.y * TILE_M;

    const uint32_t sb = smem_to_u32(smem);

    // Weight stager: 128 rows x 16 x 16B chunks = 2048 units, 8 per thread.
    auto stage_weight = [&]() {
        #pragma unroll
        for (int i = 0; i < 8; i++) {
            const int idx = tid + 256 * i;       // 0..2047
            const int row = idx >> 4;            // 0..127
            const int c16 = idx & 15;            // 16B chunk in 256B row
            const int tok = x[m0 + row];         // 16 threads/row -> broadcast
            cp_async16(sb + (uint32_t)(row * W_PITCH_BY + c16 * 16),
                       weight + (size_t)tok * DIM + n0 + c16 * 4);
        }
        cp_commit();
    };

    // Fragment pointers. ks stride 512 B; 16-row/col block stride 8192 B.
    const char* aptr = (const char*)g_Af
        + ((size_t)(blockIdx.y * 8 + warp_m * 2) * 16 * 32 + lane) * 16;
    const char* bptr = (const char*)g_Bf
        + ((size_t)(blockIdx.x * 4 + warp_n * 2) * 16 * 32 + lane) * 16;

    float acc[2][4][4];
    #pragma unroll
    for (int mt = 0; mt < 2; mt++)
        #pragma unroll
        for (int nt = 0; nt < 4; nt++)
            #pragma unroll
            for (int r = 0; r < 4; r++) acc[mt][nt][r] = 0.f;

    uint4 af[2][2];
    uint4 bv[2][2];

    auto load_frags = [&](int buf, int ks) {
        #pragma unroll
        for (int mt = 0; mt < 2; mt++)
            af[buf][mt] = *(const uint4*)(aptr + mt * 8192 + ks * 512);
        #pragma unroll
        for (int q = 0; q < 2; q++)
            bv[buf][q] = *(const uint4*)(bptr + q * 8192 + ks * 512);
    };

    // PDL: block before first read of g_Af/g_Bf.
#if __CUDA_ARCH__ >= 900
    cudaGridDependencySynchronize();
#endif

    load_frags(0, 0);

    // Mainloop: 16 k-steps, 1-step lookahead, zero barriers.
    #pragma unroll
    for (int ks = 0; ks < 16; ks++) {
        if (ks + 1 < 16) load_frags((ks + 1) & 1, ks + 1);
        if (ks == 4) stage_weight();
        const uint32_t* a0 = (const uint32_t*)&af[ks & 1][0];
        const uint32_t* a1 = (const uint32_t*)&af[ks & 1][1];
        #pragma unroll
        for (int q = 0; q < 2; q++) {
            const uint32_t* bp = (const uint32_t*)&bv[ks & 1][q];
            mma_f16(acc[0][2 * q + 0], a0, bp + 0);
            mma_f16(acc[0][2 * q + 1], a0, bp + 2);
            mma_f16(acc[1][2 * q + 0], a1, bp + 0);
            mma_f16(acc[1][2 * q + 1], a1, bp + 2);
        }
    }

    // Weight resident (staged 12 k-steps ago).
    cp_wait<0>();
    __syncthreads();

    // Epilogue: out = weight_smem + acc.
    const float* wsm = (const float*)smem;
    #pragma unroll
    for (int mt = 0; mt < 2; mt++) {
        #pragma unroll
        for (int mo = 0; mo < 2; mo++) {
            const int r = warp_m * 32 + mt * 16 + mo * 8 + group;   // 0..127
            const float* wrow = wsm + r * W_PITCH_F;
            float* orow = out + (size_t)(m0 + r) * DIM + n0;
            #pragma unroll
            for (int nt = 0; nt < 4; nt++) {
                const int col = warp_n * 32 + nt * 8 + tig * 2;     // 0..63
                float2 w = *(const float2*)(wrow + col);
                stg_cs_v2(orow + col,
                          w.x + acc[mt][nt][mo * 2 + 0],
                          w.y + acc[mt][nt][mo * 2 + 1]);
            }
        }
    }
}

// ============================================================================
// Launch
// ============================================================================
extern "C" void kernel_launch(void* const* d_in, const int* in_sizes, int n_in,
                              void* d_out, int out_size) {
    const int*   x      = (const int*)d_in[0];       // [16384] int32
    const float* weight = (const float*)d_in[1];     // [128000, 1024]
    const float* A      = (const float*)d_in[2];     // [128000, 256]
    const float* B      = (const float*)d_in[3];     // [256, 1024]
    float* out          = (float*)d_out;             // [16384, 1024]

    (void)in_sizes; (void)n_in; (void)out_size;

    // Fused prep: 64 B-fragment blocks + 2048 direct A-fragment blocks
    prep_kernel<<<64 + 2048, 256>>>(x, A, B);

    {
        static bool attr_set = false;
        if (!attr_set) {
            cudaFuncSetAttribute(lora_embed_kernel,
                                 cudaFuncAttributeMaxDynamicSharedMemorySize, SMEM_BYTES);
            attr_set = true;
        }
        cudaLaunchConfig_t cfg = {};
        cfg.gridDim  = dim3(DIM / TILE_N, M_TOTAL / TILE_M);   // (16, 128)
        cfg.blockDim = dim3(256, 1, 1);
        cfg.dynamicSmemBytes = SMEM_BYTES;
        cfg.stream = 0;
        cudaLaunchAttribute attrs[1];
        attrs[0].id = cudaLaunchAttributeProgrammaticStreamSerialization;
        attrs[0].val.programmaticStreamSerializationAllowed = 1;
        cfg.attrs = attrs;
        cfg.numAttrs = 1;
        cudaError_t err = cudaLaunchKernelEx(&cfg, lora_embed_kernel, x, weight, out);
        if (err != cudaSuccess) {
            cudaGetLastError();
            dim3 grid(DIM / TILE_N, M_TOTAL / TILE_M);
            lora_embed_kernel<<<grid, 256, SMEM_BYTES>>>(x, weight, out);
        }
    }
}